// round 5
// baseline (speedup 1.0000x reference)
#include <cuda_runtime.h>
#include <math.h>

#define Bb    16
#define Nn    1024
#define Uu    64
#define MAXD  256
#define ALPHAF 0.2f
#define ROWS  (Bb*Nn)

// ---------------- scratch (device globals; no allocation allowed) ----------
__device__ float g_h1[ROWS * 128];   // layer-1 features  (8 MB)
__device__ float g_h2[ROWS * 64];    // layer-2 features  (4 MB)
__device__ float g_rs[ROWS * 64];    // r * state         (4 MB)
__device__ float g_z [ROWS * 64];    // z gate            (4 MB)
__device__ float g_s1s[ROWS], g_s1d[ROWS];
__device__ float g_s2s[ROWS], g_s2d[ROWS];
__device__ int   g_cols[Nn * MAXD];
__device__ int   g_deg [Nn];

// ---------------- CSR build: one warp per adjacency row --------------------
__global__ void csr_kernel(const float* __restrict__ adj) {
    int warp = (blockIdx.x * blockDim.x + threadIdx.x) >> 5;
    int lane = threadIdx.x & 31;
    if (warp >= Nn) return;
    const float* arow = adj + (size_t)warp * Nn;
    int base = 0;
    for (int c0 = 0; c0 < Nn; c0 += 32) {
        float v = arow[c0 + lane];
        unsigned m = __ballot_sync(0xffffffffu, v > 0.f);
        int rank = __popc(m & ((1u << lane) - 1));
        int pos  = base + rank;
        if (v > 0.f && pos < MAXD) g_cols[warp * MAXD + pos] = c0 + lane;
        base += __popc(m);
    }
    if (lane == 0) g_deg[warp] = base < MAXD ? base : MAXD;
}

// ---------------- GEMM: H = [Xp | Sp] @ W,   M=16384, K=128, N=FOUT --------
// SECOND: second input half is the device-global g_rs (resolved IN DEVICE CODE
// — passing a __device__ symbol address from host is UB and was the R3 bug).
template<int FOUT, bool SECOND>
__global__ void gemm_kernel(const float* __restrict__ Xp,
                            const float* __restrict__ SpArg,
                            const float* __restrict__ W) {
    constexpr int BM = 64, BK = 32, TM = 8, TN = FOUT / 32;
    __shared__ float xs[BM][BK + 1];
    __shared__ float ws[BK][FOUT];
    const float* Sp = SECOND ? (const float*)g_rs : SpArg;
    float* H = SECOND ? g_h2 : g_h1;

    int tid = threadIdx.x;           // 256 threads
    int tx  = tid & 31;              // col group
    int ty  = tid >> 5;              // row group, [0,8)
    int row0 = blockIdx.x * BM;

    float acc[TM][TN];
#pragma unroll
    for (int r = 0; r < TM; r++)
#pragma unroll
        for (int c = 0; c < TN; c++) acc[r][c] = 0.f;

    for (int kt = 0; kt < 128; kt += BK) {
        // load X1 tile (built on the fly from the two halves)
        for (int l = tid; l < BM * BK; l += 256) {
            int r = l >> 5, k = l & 31;
            int gk = kt + k;
            int grow = row0 + r;
            float v = (gk < 64) ? Xp[(size_t)grow * 64 + gk]
                                : Sp[(size_t)grow * 64 + gk - 64];
            xs[r][k] = v;
        }
        // load W tile
        for (int l = tid; l < BK * FOUT; l += 256) {
            int k = l / FOUT, c = l % FOUT;
            ws[k][c] = W[(size_t)(kt + k) * FOUT + c];
        }
        __syncthreads();
#pragma unroll
        for (int k = 0; k < BK; k++) {
            float a[TM];
#pragma unroll
            for (int r = 0; r < TM; r++) a[r] = xs[ty * TM + r][k];
            float b[TN];
#pragma unroll
            for (int c = 0; c < TN; c++) b[c] = ws[k][tx + 32 * c];
#pragma unroll
            for (int r = 0; r < TM; r++)
#pragma unroll
                for (int c = 0; c < TN; c++) acc[r][c] += a[r] * b[c];
        }
        __syncthreads();
    }
#pragma unroll
    for (int r = 0; r < TM; r++)
#pragma unroll
        for (int c = 0; c < TN; c++)
            H[(size_t)(row0 + ty * TM + r) * FOUT + tx + 32 * c] = acc[r][c];
}

// ---------------- per-row attention scores: s = h . a halves ---------------
template<int F, bool SECOND>
__global__ void score_kernel(const float* __restrict__ a) {
    int gw = (blockIdx.x * blockDim.x + threadIdx.x) >> 5;
    if (gw >= ROWS) return;
    int lane = threadIdx.x & 31;
    const float* H = SECOND ? g_h2 : g_h1;
    float ps = 0.f, pd = 0.f;
    if (F == 128) {
        float4 h4 = ((const float4*)(H + (size_t)gw * 128))[lane];
        float4 as = ((const float4*)a)[lane];
        float4 ad = ((const float4*)(a + 128))[lane];
        ps = h4.x*as.x + h4.y*as.y + h4.z*as.z + h4.w*as.w;
        pd = h4.x*ad.x + h4.y*ad.y + h4.z*ad.z + h4.w*ad.w;
    } else {
        float2 h2v = ((const float2*)(H + (size_t)gw * 64))[lane];
        float2 as  = ((const float2*)a)[lane];
        float2 ad  = ((const float2*)(a + 64))[lane];
        ps = h2v.x*as.x + h2v.y*as.y;
        pd = h2v.x*ad.x + h2v.y*ad.y;
    }
#pragma unroll
    for (int o = 16; o; o >>= 1) {
        ps += __shfl_xor_sync(0xffffffffu, ps, o);
        pd += __shfl_xor_sync(0xffffffffu, pd, o);
    }
    if (lane == 0) {
        if (SECOND) { g_s2s[gw] = ps; g_s2d[gw] = pd; }
        else        { g_s1s[gw] = ps; g_s1d[gw] = pd; }
    }
}

__device__ __forceinline__ float lrelu(float x) { return x > 0.f ? x : ALPHAF * x; }

// ---------------- layer-1 aggregation: softmax gather + sigmoid gate -------
__global__ void agg1_kernel(const float* __restrict__ state) {
    int gw = (blockIdx.x * blockDim.x + threadIdx.x) >> 5;
    if (gw >= ROWS) return;
    int lane = threadIdx.x & 31;
    int b = gw >> 10, i = gw & (Nn - 1);
    int bN = b * Nn;
    int d = g_deg[i];
    const int* cl = g_cols + i * MAXD;
    float si = g_s1s[gw];

    float m = -1e30f;
    for (int t = lane; t < d; t += 32)
        m = fmaxf(m, lrelu(si + g_s1d[bN + cl[t]]));
#pragma unroll
    for (int o = 16; o; o >>= 1) m = fmaxf(m, __shfl_xor_sync(0xffffffffu, m, o));

    float Zp = 0.f;
    for (int t = lane; t < d; t += 32)
        Zp += __expf(lrelu(si + g_s1d[bN + cl[t]]) - m);
#pragma unroll
    for (int o = 16; o; o >>= 1) Zp += __shfl_xor_sync(0xffffffffu, Zp, o);
    float invZ = 1.f / Zp;

    float4 acc = make_float4(0.f, 0.f, 0.f, 0.f);
    for (int t = 0; t < d; t++) {
        int j = cl[t];
        float w = __expf(lrelu(si + g_s1d[bN + j]) - m) * invZ;
        float4 hv = *((const float4*)(g_h1 + (size_t)(bN + j) * 128) + lane);
        acc.x += w * hv.x; acc.y += w * hv.y; acc.z += w * hv.z; acc.w += w * hv.w;
    }
    float4 g;
    g.x = 1.f / (1.f + __expf(-acc.x));
    g.y = 1.f / (1.f + __expf(-acc.y));
    g.z = 1.f / (1.f + __expf(-acc.z));
    g.w = 1.f / (1.f + __expf(-acc.w));
    if (lane < 16) {   // features [0,64): r -> store r*state
        float4 st = ((const float4*)(state + (size_t)gw * 64))[lane];
        float4 o;
        o.x = g.x * st.x; o.y = g.y * st.y; o.z = g.z * st.z; o.w = g.w * st.w;
        ((float4*)(g_rs + (size_t)gw * 64))[lane] = o;
    } else {           // features [64,128): z
        ((float4*)(g_z + (size_t)gw * 64))[lane - 16] = g;
    }
}

// ---------------- layer-2 aggregation: softmax gather + tanh + GRU blend ---
__global__ void agg2_kernel(const float* __restrict__ state, float* __restrict__ out) {
    int gw = (blockIdx.x * blockDim.x + threadIdx.x) >> 5;
    if (gw >= ROWS) return;
    int lane = threadIdx.x & 31;
    int b = gw >> 10, i = gw & (Nn - 1);
    int bN = b * Nn;
    int d = g_deg[i];
    const int* cl = g_cols + i * MAXD;
    float si = g_s2s[gw];

    float m = -1e30f;
    for (int t = lane; t < d; t += 32)
        m = fmaxf(m, lrelu(si + g_s2d[bN + cl[t]]));
#pragma unroll
    for (int o = 16; o; o >>= 1) m = fmaxf(m, __shfl_xor_sync(0xffffffffu, m, o));

    float Zp = 0.f;
    for (int t = lane; t < d; t += 32)
        Zp += __expf(lrelu(si + g_s2d[bN + cl[t]]) - m);
#pragma unroll
    for (int o = 16; o; o >>= 1) Zp += __shfl_xor_sync(0xffffffffu, Zp, o);
    float invZ = 1.f / Zp;

    float2 acc = make_float2(0.f, 0.f);
    for (int t = 0; t < d; t++) {
        int j = cl[t];
        float w = __expf(lrelu(si + g_s2d[bN + j]) - m) * invZ;
        float2 hv = *((const float2*)(g_h2 + (size_t)(bN + j) * 64) + lane);
        acc.x += w * hv.x; acc.y += w * hv.y;
    }
    float tx = tanhf(acc.x), ty = tanhf(acc.y);
    float2 zz = ((const float2*)(g_z    + (size_t)gw * 64))[lane];
    float2 st = ((const float2*)(state  + (size_t)gw * 64))[lane];
    float2 o;
    o.x = zz.x * st.x + (1.f - zz.x) * tx;
    o.y = zz.y * st.y + (1.f - zz.y) * ty;
    ((float2*)(out + (size_t)gw * 64))[lane] = o;
}

// ---------------- launch ---------------------------------------------------
extern "C" void kernel_launch(void* const* d_in, const int* in_sizes, int n_in,
                              void* d_out, int out_size) {
    const float* X     = (const float*)d_in[0];
    const float* state = (const float*)d_in[1];
    const float* adj   = (const float*)d_in[2];
    const float* W1    = (const float*)d_in[3];
    const float* a1    = (const float*)d_in[4];
    const float* W2    = (const float*)d_in[5];
    const float* a2    = (const float*)d_in[6];
    float* out = (float*)d_out;

    csr_kernel<<<(Nn * 32 + 255) / 256, 256>>>(adj);
    gemm_kernel<128, false><<<ROWS / 64, 256>>>(X, state, W1);
    score_kernel<128, false><<<(ROWS * 32 + 255) / 256, 256>>>(a1);
    agg1_kernel<<<(ROWS * 32 + 255) / 256, 256>>>(state);
    gemm_kernel<64, true><<<ROWS / 64, 256>>>(X, /*unused*/nullptr, W2);
    score_kernel<64, true><<<(ROWS * 32 + 255) / 256, 256>>>(a2);
    agg2_kernel<<<(ROWS * 32 + 255) / 256, 256>>>(state, out);
}

// round 6
// speedup vs baseline: 1.1719x; 1.1719x over previous
#include <cuda_runtime.h>
#include <math.h>

#define Bb    16
#define Nn    1024
#define Uu    64
#define MAXD  256
#define ALPHAF 0.2f
#define ROWS  (Bb*Nn)

// ---------------- scratch (device globals; no allocation allowed) ----------
__device__ float g_h1[ROWS * 128];   // layer-1 features  (8 MB)
__device__ float g_h2[ROWS * 64];    // layer-2 features  (4 MB)
__device__ float g_rs[ROWS * 64];    // r * state         (4 MB)
__device__ float g_z [ROWS * 64];    // z gate            (4 MB)
__device__ float g_s1s[ROWS], g_s1d[ROWS];
__device__ float g_s2s[ROWS], g_s2d[ROWS];
__device__ int   g_cols[Nn * MAXD];
__device__ int   g_deg [Nn];

__device__ __forceinline__ float lrelu(float x) { return x > 0.f ? x : ALPHAF * x; }

// ---------------- CSR build: one warp per adjacency row --------------------
__global__ void csr_kernel(const float* __restrict__ adj) {
    int warp = (blockIdx.x * blockDim.x + threadIdx.x) >> 5;
    int lane = threadIdx.x & 31;
    if (warp >= Nn) return;
    const float* arow = adj + (size_t)warp * Nn;
    int base = 0;
    for (int c0 = 0; c0 < Nn; c0 += 32) {
        float v = arow[c0 + lane];
        unsigned m = __ballot_sync(0xffffffffu, v > 0.f);
        int rank = __popc(m & ((1u << lane) - 1));
        int pos  = base + rank;
        if (v > 0.f && pos < MAXD) g_cols[warp * MAXD + pos] = c0 + lane;
        base += __popc(m);
    }
    if (lane == 0) g_deg[warp] = base < MAXD ? base : MAXD;
}

// ---------------- GEMM1: h1 = [X|state] @ W1 (+ fused scores) --------------
// BM=128, BN=128, BK=16, 256 threads, 8x8 per thread.
__global__ __launch_bounds__(256) void gemm1_kernel(
        const float* __restrict__ X, const float* __restrict__ S,
        const float* __restrict__ W, const float* __restrict__ a) {
    __shared__ float xs[16][132];    // transposed X tile (padded)
    __shared__ float ws[16][128];
    int tid = threadIdx.x;
    int tx = tid & 15, ty = tid >> 4;
    int row0 = blockIdx.x * 128;

    float acc[8][8];
#pragma unroll
    for (int r = 0; r < 8; r++)
#pragma unroll
        for (int c = 0; c < 8; c++) acc[r][c] = 0.f;

    for (int kt = 0; kt < 128; kt += 16) {
        // X tile: 128 rows x 16 k = 512 float4, 2 per thread, store transposed
#pragma unroll
        for (int i = 0; i < 2; i++) {
            int l = tid + i * 256;
            int r = l >> 2, kq = (l & 3) * 4;
            int gk = kt + kq;
            const float* src = (gk < 64) ? X + (size_t)(row0 + r) * 64 + gk
                                         : S + (size_t)(row0 + r) * 64 + gk - 64;
            float4 v = *(const float4*)src;
            xs[kq + 0][r] = v.x; xs[kq + 1][r] = v.y;
            xs[kq + 2][r] = v.z; xs[kq + 3][r] = v.w;
        }
        // W tile: 16 x 128 = 512 float4, 2 per thread
#pragma unroll
        for (int i = 0; i < 2; i++) {
            int l = tid + i * 256;
            int k = l >> 5, c = (l & 31) * 4;
            *(float4*)&ws[k][c] = *(const float4*)&W[(size_t)(kt + k) * 128 + c];
        }
        __syncthreads();
#pragma unroll
        for (int k = 0; k < 16; k++) {
            float av[8], bv[8];
            *(float4*)&av[0] = *(const float4*)&xs[k][ty * 8];
            *(float4*)&av[4] = *(const float4*)&xs[k][ty * 8 + 4];
            *(float4*)&bv[0] = *(const float4*)&ws[k][tx * 8];
            *(float4*)&bv[4] = *(const float4*)&ws[k][tx * 8 + 4];
#pragma unroll
            for (int r = 0; r < 8; r++)
#pragma unroll
                for (int c = 0; c < 8; c++) acc[r][c] += av[r] * bv[c];
        }
        __syncthreads();
    }
    // epilogue: store h1 + fused attention-score partials
    float asrc[8], adst[8];
#pragma unroll
    for (int c = 0; c < 8; c++) {
        asrc[c] = __ldg(a + tx * 8 + c);
        adst[c] = __ldg(a + 128 + tx * 8 + c);
    }
#pragma unroll
    for (int r = 0; r < 8; r++) {
        int row = row0 + ty * 8 + r;
        float4 v0 = make_float4(acc[r][0], acc[r][1], acc[r][2], acc[r][3]);
        float4 v1 = make_float4(acc[r][4], acc[r][5], acc[r][6], acc[r][7]);
        *(float4*)&g_h1[(size_t)row * 128 + tx * 8]     = v0;
        *(float4*)&g_h1[(size_t)row * 128 + tx * 8 + 4] = v1;
        float ps = 0.f, pd = 0.f;
#pragma unroll
        for (int c = 0; c < 8; c++) { ps += acc[r][c] * asrc[c]; pd += acc[r][c] * adst[c]; }
#pragma unroll
        for (int o = 8; o; o >>= 1) {
            ps += __shfl_xor_sync(0xffffffffu, ps, o);
            pd += __shfl_xor_sync(0xffffffffu, pd, o);
        }
        if (tx == 0) { g_s1s[row] = ps; g_s1d[row] = pd; }
    }
}

// ---------------- GEMM2: h2 = [X|r*state] @ W2 (+ fused scores) ------------
// BM=128, BN=64, BK=16, 256 threads, 8x4 per thread.
__global__ __launch_bounds__(256) void gemm2_kernel(
        const float* __restrict__ X,
        const float* __restrict__ W, const float* __restrict__ a) {
    __shared__ float xs[16][132];
    __shared__ float ws[16][64];
    const float* S = (const float*)g_rs;    // device-symbol resolved in device code
    int tid = threadIdx.x;
    int tx = tid & 15, ty = tid >> 4;
    int row0 = blockIdx.x * 128;

    float acc[8][4];
#pragma unroll
    for (int r = 0; r < 8; r++)
#pragma unroll
        for (int c = 0; c < 4; c++) acc[r][c] = 0.f;

    for (int kt = 0; kt < 128; kt += 16) {
#pragma unroll
        for (int i = 0; i < 2; i++) {
            int l = tid + i * 256;
            int r = l >> 2, kq = (l & 3) * 4;
            int gk = kt + kq;
            const float* src = (gk < 64) ? X + (size_t)(row0 + r) * 64 + gk
                                         : S + (size_t)(row0 + r) * 64 + gk - 64;
            float4 v = *(const float4*)src;
            xs[kq + 0][r] = v.x; xs[kq + 1][r] = v.y;
            xs[kq + 2][r] = v.z; xs[kq + 3][r] = v.w;
        }
        {   // W tile: 16 x 64 = 256 float4, 1 per thread
            int k = tid >> 4, c = (tid & 15) * 4;
            *(float4*)&ws[k][c] = *(const float4*)&W[(size_t)(kt + k) * 64 + c];
        }
        __syncthreads();
#pragma unroll
        for (int k = 0; k < 16; k++) {
            float av[8], bv[4];
            *(float4*)&av[0] = *(const float4*)&xs[k][ty * 8];
            *(float4*)&av[4] = *(const float4*)&xs[k][ty * 8 + 4];
            *(float4*)&bv[0] = *(const float4*)&ws[k][tx * 4];
#pragma unroll
            for (int r = 0; r < 8; r++)
#pragma unroll
                for (int c = 0; c < 4; c++) acc[r][c] += av[r] * bv[c];
        }
        __syncthreads();
    }
    float asrc[4], adst[4];
#pragma unroll
    for (int c = 0; c < 4; c++) {
        asrc[c] = __ldg(a + tx * 4 + c);
        adst[c] = __ldg(a + 64 + tx * 4 + c);
    }
#pragma unroll
    for (int r = 0; r < 8; r++) {
        int row = row0 + ty * 8 + r;
        float4 v0 = make_float4(acc[r][0], acc[r][1], acc[r][2], acc[r][3]);
        *(float4*)&g_h2[(size_t)row * 64 + tx * 4] = v0;
        float ps = 0.f, pd = 0.f;
#pragma unroll
        for (int c = 0; c < 4; c++) { ps += acc[r][c] * asrc[c]; pd += acc[r][c] * adst[c]; }
#pragma unroll
        for (int o = 8; o; o >>= 1) {
            ps += __shfl_xor_sync(0xffffffffu, ps, o);
            pd += __shfl_xor_sync(0xffffffffu, pd, o);
        }
        if (tx == 0) { g_s2s[row] = ps; g_s2d[row] = pd; }
    }
}

// ---------------- layer-1 aggregation: shared-weight softmax gather --------
__global__ __launch_bounds__(256) void agg1_kernel(const float* __restrict__ state) {
    __shared__ float wsh[8][MAXD];
    int warp = threadIdx.x >> 5;
    int lane = threadIdx.x & 31;
    int gw = blockIdx.x * 8 + warp;
    int b = gw >> 10, i = gw & (Nn - 1);
    int bN = b * Nn;
    int d = g_deg[i];
    const int* cl = g_cols + i * MAXD;
    float si = g_s1s[gw];
    float* w = wsh[warp];

    float m = -1e30f;
    for (int t = lane; t < d; t += 32) {
        float e = lrelu(si + __ldg(&g_s1d[bN + cl[t]]));
        w[t] = e;
        m = fmaxf(m, e);
    }
#pragma unroll
    for (int o = 16; o; o >>= 1) m = fmaxf(m, __shfl_xor_sync(0xffffffffu, m, o));
    __syncwarp();
    float Z = 0.f;
    for (int t = lane; t < d; t += 32) { float p = __expf(w[t] - m); w[t] = p; Z += p; }
#pragma unroll
    for (int o = 16; o; o >>= 1) Z += __shfl_xor_sync(0xffffffffu, Z, o);
    float invZ = 1.f / Z;
    for (int t = lane; t < d; t += 32) w[t] *= invZ;
    __syncwarp();

    const float4* H = (const float4*)g_h1;
    float4 acc = make_float4(0.f, 0.f, 0.f, 0.f);
    int t = 0;
    for (; t + 4 <= d; t += 4) {
        int j0 = cl[t], j1 = cl[t+1], j2 = cl[t+2], j3 = cl[t+3];
        float w0 = w[t], w1 = w[t+1], w2 = w[t+2], w3 = w[t+3];
        float4 h0 = H[(size_t)(bN + j0) * 32 + lane];
        float4 h1 = H[(size_t)(bN + j1) * 32 + lane];
        float4 h2 = H[(size_t)(bN + j2) * 32 + lane];
        float4 h3 = H[(size_t)(bN + j3) * 32 + lane];
        acc.x += w0*h0.x + w1*h1.x + w2*h2.x + w3*h3.x;
        acc.y += w0*h0.y + w1*h1.y + w2*h2.y + w3*h3.y;
        acc.z += w0*h0.z + w1*h1.z + w2*h2.z + w3*h3.z;
        acc.w += w0*h0.w + w1*h1.w + w2*h2.w + w3*h3.w;
    }
    for (; t < d; t++) {
        float wt = w[t];
        float4 hv = H[(size_t)(bN + cl[t]) * 32 + lane];
        acc.x += wt*hv.x; acc.y += wt*hv.y; acc.z += wt*hv.z; acc.w += wt*hv.w;
    }
    float4 g;
    g.x = 1.f / (1.f + __expf(-acc.x));
    g.y = 1.f / (1.f + __expf(-acc.y));
    g.z = 1.f / (1.f + __expf(-acc.z));
    g.w = 1.f / (1.f + __expf(-acc.w));
    if (lane < 16) {   // features [0,64): r -> store r*state
        float4 st = ((const float4*)(state + (size_t)gw * 64))[lane];
        float4 o;
        o.x = g.x*st.x; o.y = g.y*st.y; o.z = g.z*st.z; o.w = g.w*st.w;
        ((float4*)(g_rs + (size_t)gw * 64))[lane] = o;
    } else {           // features [64,128): z
        ((float4*)(g_z + (size_t)gw * 64))[lane - 16] = g;
    }
}

// ---------------- layer-2 aggregation + GRU blend --------------------------
__global__ __launch_bounds__(256) void agg2_kernel(const float* __restrict__ state,
                                                   float* __restrict__ out) {
    __shared__ float wsh[8][MAXD];
    int warp = threadIdx.x >> 5;
    int lane = threadIdx.x & 31;
    int gw = blockIdx.x * 8 + warp;
    int b = gw >> 10, i = gw & (Nn - 1);
    int bN = b * Nn;
    int d = g_deg[i];
    const int* cl = g_cols + i * MAXD;
    float si = g_s2s[gw];
    float* w = wsh[warp];

    float m = -1e30f;
    for (int t = lane; t < d; t += 32) {
        float e = lrelu(si + __ldg(&g_s2d[bN + cl[t]]));
        w[t] = e;
        m = fmaxf(m, e);
    }
#pragma unroll
    for (int o = 16; o; o >>= 1) m = fmaxf(m, __shfl_xor_sync(0xffffffffu, m, o));
    __syncwarp();
    float Z = 0.f;
    for (int t = lane; t < d; t += 32) { float p = __expf(w[t] - m); w[t] = p; Z += p; }
#pragma unroll
    for (int o = 16; o; o >>= 1) Z += __shfl_xor_sync(0xffffffffu, Z, o);
    float invZ = 1.f / Z;
    for (int t = lane; t < d; t += 32) w[t] *= invZ;
    __syncwarp();

    const float2* H = (const float2*)g_h2;
    float2 acc = make_float2(0.f, 0.f);
    int t = 0;
    for (; t + 4 <= d; t += 4) {
        int j0 = cl[t], j1 = cl[t+1], j2 = cl[t+2], j3 = cl[t+3];
        float w0 = w[t], w1 = w[t+1], w2 = w[t+2], w3 = w[t+3];
        float2 h0 = H[(size_t)(bN + j0) * 32 + lane];
        float2 h1 = H[(size_t)(bN + j1) * 32 + lane];
        float2 h2 = H[(size_t)(bN + j2) * 32 + lane];
        float2 h3 = H[(size_t)(bN + j3) * 32 + lane];
        acc.x += w0*h0.x + w1*h1.x + w2*h2.x + w3*h3.x;
        acc.y += w0*h0.y + w1*h1.y + w2*h2.y + w3*h3.y;
    }
    for (; t < d; t++) {
        float wt = w[t];
        float2 hv = H[(size_t)(bN + cl[t]) * 32 + lane];
        acc.x += wt*hv.x; acc.y += wt*hv.y;
    }
    float tx = tanhf(acc.x), ty = tanhf(acc.y);
    float2 zz = ((const float2*)(g_z   + (size_t)gw * 64))[lane];
    float2 st = ((const float2*)(state + (size_t)gw * 64))[lane];
    float2 o;
    o.x = zz.x * st.x + (1.f - zz.x) * tx;
    o.y = zz.y * st.y + (1.f - zz.y) * ty;
    ((float2*)(out + (size_t)gw * 64))[lane] = o;
}

// ---------------- launch ---------------------------------------------------
extern "C" void kernel_launch(void* const* d_in, const int* in_sizes, int n_in,
                              void* d_out, int out_size) {
    const float* X     = (const float*)d_in[0];
    const float* state = (const float*)d_in[1];
    const float* adj   = (const float*)d_in[2];
    const float* W1    = (const float*)d_in[3];
    const float* a1    = (const float*)d_in[4];
    const float* W2    = (const float*)d_in[5];
    const float* a2    = (const float*)d_in[6];
    float* out = (float*)d_out;

    csr_kernel<<<Nn * 32 / 256, 256>>>(adj);
    gemm1_kernel<<<ROWS / 128, 256>>>(X, state, W1, a1);
    agg1_kernel<<<ROWS / 8, 256>>>(state);
    gemm2_kernel<<<ROWS / 128, 256>>>(X, W2, a2);
    agg2_kernel<<<ROWS / 8, 256>>>(state, out);
}